// round 4
// baseline (speedup 1.0000x reference)
#include <cuda_runtime.h>
#include <math.h>

#define BB 64
#define TT 512
#define DD 512
#define HH 1024

#define NCTA    128
#define JB      16          // j columns per CTA
#define BHALF   32          // batch rows per CTA
#define HSS     132         // hs row stride in floats (16B-aligned, conflict-free)
#define CHUNK_K 128         // k per staged chunk
#define NCHUNK  (HH / CHUNK_K)
#define NKQ     (HH / 4)    // 256 k-quads total
#define KQ_CHUNK (CHUNK_K / 4)   // 32 k-quads per chunk

#define WS_FLOATS (3 * NKQ * JB * 4)          // 49152
#define HS_FLOATS (BHALF * HSS)               // 4224
#define SMEM_BYTES ((WS_FLOATS + HS_FLOATS) * 4)

typedef unsigned long long u64;

// Scratch (static device globals — allocation-free kernel_launch)
__device__ float g_XG[3 * TT * BB * HH];   // [g][t][b][h] precomputed x-projections (+ input bias)
__device__ float g_h[2][BB * HH];          // ping-pong hidden state
__device__ unsigned int g_bar_count = 0;
__device__ unsigned int g_bar_gen = 0;

__device__ __forceinline__ void ffma2(u64& d, u64 a, u64 b) {
    asm("fma.rn.f32x2 %0, %1, %2, %0;" : "+l"(d) : "l"(a), "l"(b));
}
__device__ __forceinline__ float pairsum(u64 v) {
    return __uint_as_float((unsigned)(v & 0xffffffffull)) +
           __uint_as_float((unsigned)(v >> 32));
}
__device__ __forceinline__ u64 splat2(float a) {
    u64 r;
    asm("mov.b64 %0, {%1, %1};" : "=l"(r) : "f"(a));
    return r;
}

// All 128 CTAs co-resident (1 CTA/SM) -> spin barrier safe. acq/rel, no membars.
__device__ __forceinline__ void grid_barrier() {
    __syncthreads();
    if (threadIdx.x == 0) {
        unsigned gen;
        asm volatile("ld.relaxed.gpu.global.u32 %0, [%1];" : "=r"(gen) : "l"(&g_bar_gen));
        unsigned old;
        asm volatile("atom.acq_rel.gpu.global.add.u32 %0, [%1], 1;" : "=r"(old) : "l"(&g_bar_count));
        if (old == NCTA - 1) {
            asm volatile("st.relaxed.gpu.global.u32 [%0], %1;" :: "l"(&g_bar_count), "r"(0u));
            asm volatile("st.release.gpu.global.u32 [%0], %1;" :: "l"(&g_bar_gen), "r"(gen + 1));
        } else {
            unsigned cur;
            do {
                asm volatile("ld.acquire.gpu.global.u32 %0, [%1];" : "=r"(cur) : "l"(&g_bar_gen));
            } while (cur == gen);
        }
    }
    __syncthreads();
}

// ---------------------------------------------------------------------------
// Precompute xg[g][t][b][:] = x[b][t][:] @ W_gx + b_gx  (128x128x16, FFMA2)
// acc2[ip][j]: row-pair (2*ip, 2*ip+1) packed in f32x2; a-pairs free from float4 A.
// ---------------------------------------------------------------------------
__global__ __launch_bounds__(256) void xproj_kernel(
    const float* __restrict__ x,
    const float* __restrict__ Wz, const float* __restrict__ Wr, const float* __restrict__ Wn,
    const float* __restrict__ bz, const float* __restrict__ br, const float* __restrict__ bn) {

    int g = blockIdx.z;
    const float* Wm   = (g == 0) ? Wz : ((g == 1) ? Wr : Wn);
    const float* bias = (g == 0) ? bz : ((g == 1) ? br : bn);

    __shared__ float As[16][128];   // [k][m]
    __shared__ float Bs[16][128];   // [k][n]

    int m0 = blockIdx.x * 128;
    int n0 = blockIdx.y * 128;
    int tid = threadIdx.x;
    int txq = tid % 16, tyq = tid / 16;

    u64 acc2[4][8];
#pragma unroll
    for (int i = 0; i < 4; i++)
#pragma unroll
        for (int j = 0; j < 8; j++) acc2[i][j] = 0ull;

    for (int k0 = 0; k0 < DD; k0 += 16) {
#pragma unroll
        for (int l = 0; l < 2; l++) {
            int idx = tid + l * 256;
            int row = idx >> 2;
            int kk  = (idx & 3) * 4;
            float4 v = *(const float4*)&x[(size_t)(m0 + row) * DD + k0 + kk];
            As[kk + 0][row] = v.x;
            As[kk + 1][row] = v.y;
            As[kk + 2][row] = v.z;
            As[kk + 3][row] = v.w;
        }
#pragma unroll
        for (int l = 0; l < 2; l++) {
            int idx = tid + l * 256;
            int row = idx >> 5;
            int nn  = (idx & 31) * 4;
            *(float4*)&Bs[row][nn] = *(const float4*)&Wm[(size_t)(k0 + row) * HH + n0 + nn];
        }
        __syncthreads();
#pragma unroll
        for (int k = 0; k < 16; k++) {
            const u64* Ap = (const u64*)&As[k][tyq * 8];   // 4 natural row-pairs
            u64 ap0 = Ap[0], ap1 = Ap[1], ap2 = Ap[2], ap3 = Ap[3];
            float4 b0 = *(const float4*)&Bs[k][txq * 8];
            float4 b1 = *(const float4*)&Bs[k][txq * 8 + 4];
            u64 bs[8];
            bs[0] = splat2(b0.x); bs[1] = splat2(b0.y); bs[2] = splat2(b0.z); bs[3] = splat2(b0.w);
            bs[4] = splat2(b1.x); bs[5] = splat2(b1.y); bs[6] = splat2(b1.z); bs[7] = splat2(b1.w);
#pragma unroll
            for (int j = 0; j < 8; j++) {
                ffma2(acc2[0][j], ap0, bs[j]);
                ffma2(acc2[1][j], ap1, bs[j]);
                ffma2(acc2[2][j], ap2, bs[j]);
                ffma2(acc2[3][j], ap3, bs[j]);
            }
        }
        __syncthreads();
    }

#pragma unroll
    for (int ip = 0; ip < 4; ip++) {
#pragma unroll
        for (int half = 0; half < 2; half++) {
            int m  = m0 + tyq * 8 + ip * 2 + half;
            int bb = m / TT;
            int tt = m % TT;
            float* outr = &g_XG[(((size_t)g * TT + tt) * BB + bb) * HH + n0 + txq * 8];
#pragma unroll
            for (int j = 0; j < 8; j++) {
                u64 v = acc2[ip][j];
                float f = half ? __uint_as_float((unsigned)(v >> 32))
                               : __uint_as_float((unsigned)(v & 0xffffffffull));
                outr[j] = f + bias[n0 + txq * 8 + j];
            }
        }
    }
}

// ---------------------------------------------------------------------------
// Persistent GRU scan. 128 CTAs = 64 j-blocks x 2 batch-halves.
// 2-D warp tiling: warp = (j-quad, row-half); lane = 4 j x 8 rows; thread = 2 rows.
// W resident in SMEM ([g][kq][j] float4 over k), h staged per 128-k chunk.
// ---------------------------------------------------------------------------
__global__ __launch_bounds__(256, 1) void gru_scan_kernel(
    float* __restrict__ out,
    const float* __restrict__ Wzh, const float* __restrict__ Wrh, const float* __restrict__ Wnh,
    const float* __restrict__ bzh, const float* __restrict__ brh, const float* __restrict__ bnh)
{
    extern __shared__ float smem[];
    float* ws = smem;                    // [g][kq][j][4]  (k-quad per float4)
    float* hs = smem + WS_FLOATS;        // [b_local][HSS]

    const int tid  = threadIdx.x;
    const int jb   = blockIdx.x & 63;
    const int bb   = blockIdx.x >> 6;
    const int warp = tid >> 5;
    const int lane = tid & 31;

    const int jq   = warp & 3;           // j-quad of this warp
    const int rh   = warp >> 2;          // row-half of this warp
    const int jl   = lane & 3;
    const int rl   = lane >> 2;          // 0..7
    const int j    = jq * 4 + jl;        // 0..15
    const int rA   = rh * 16 + rl;       // local rows rA, rA+8
    const int rB   = rA + 8;
    const int jcol = jb * JB + j;
    const int rowA = bb * BHALF + rA;
    const int rowB = bb * BHALF + rB;

    // ---- load this CTA's W slice into SMEM (once) ----
    for (int e = tid; e < 3 * HH * JB; e += 256) {
        int jj = e & (JB - 1);
        int k  = (e >> 4) & (HH - 1);
        int g  = e >> 14;
        const float* Wsrc = (g == 0) ? Wzh : ((g == 1) ? Wrh : Wnh);
        ws[((g * NKQ + (k >> 2)) * JB + jj) * 4 + (k & 3)] =
            Wsrc[(size_t)k * HH + jb * JB + jj];
    }
    // ---- zero h[0] (disjoint slices) ----
    for (int e = tid; e < (BB * HH) / NCTA; e += 256)
        g_h[0][blockIdx.x * ((BB * HH) / NCTA) + e] = 0.0f;
    grid_barrier();

    const float bz = bzh[jcol], br = brh[jcol], bn = bnh[jcol];
    const ulonglong2* ws2 = (const ulonglong2*)ws;

    for (int t = 0; t < TT; t++) {
        const float* __restrict__ h_in  = g_h[t & 1];
        float* __restrict__ h_out = (t == TT - 1) ? out : g_h[(t + 1) & 1];

        // epilogue operands prefetched at step start
        const float* xz = g_XG + ((size_t)(0 * TT + t)) * (BB * HH);
        const float* xr = g_XG + ((size_t)(1 * TT + t)) * (BB * HH);
        const float* xn = g_XG + ((size_t)(2 * TT + t)) * (BB * HH);
        float xzA = xz[(size_t)rowA * HH + jcol], xzB = xz[(size_t)rowB * HH + jcol];
        float xrA = xr[(size_t)rowA * HH + jcol], xrB = xr[(size_t)rowB * HH + jcol];
        float xnA = xn[(size_t)rowA * HH + jcol], xnB = xn[(size_t)rowB * HH + jcol];
        float hpA = __ldcg(&h_in[(size_t)rowA * HH + jcol]);
        float hpB = __ldcg(&h_in[(size_t)rowB * HH + jcol]);

        u64 azA = 0, azB = 0, arA = 0, arB = 0, anA = 0, anB = 0;

        // register-double-buffered h staging: 4 float4 per thread per chunk
        float4 pf[4];
        {
            const int c4 = lane * 4;
#pragma unroll
            for (int l = 0; l < 4; l++) {
                int rowl = warp + l * 8;
                pf[l] = __ldcg((const float4*)&h_in[(size_t)(bb * BHALF + rowl) * HH + c4]);
            }
        }

        for (int ch = 0; ch < NCHUNK; ch++) {
            __syncthreads();
            {
                const int c4 = lane * 4;
#pragma unroll
                for (int l = 0; l < 4; l++) {
                    int rowl = warp + l * 8;
                    *(float4*)&hs[rowl * HSS + c4] = pf[l];
                }
            }
            __syncthreads();
            if (ch + 1 < NCHUNK) {
                const int kcn = (ch + 1) * CHUNK_K;
                const int c4 = lane * 4;
#pragma unroll
                for (int l = 0; l < 4; l++) {
                    int rowl = warp + l * 8;
                    pf[l] = __ldcg((const float4*)&h_in[(size_t)(bb * BHALF + rowl) * HH + kcn + c4]);
                }
            }

            const int kq0 = ch * KQ_CHUNK;
            const ulonglong2* hAp = (const ulonglong2*)(hs + rA * HSS);
            const ulonglong2* hBp = (const ulonglong2*)(hs + rB * HSS);
            const ulonglong2* wzp = ws2 + ((size_t)(0 * NKQ + kq0) * JB + j);
            const ulonglong2* wrp = ws2 + ((size_t)(1 * NKQ + kq0) * JB + j);
            const ulonglong2* wnp = ws2 + ((size_t)(2 * NKQ + kq0) * JB + j);

#pragma unroll
            for (int kql = 0; kql < KQ_CHUNK; kql++) {
                ulonglong2 ha = hAp[kql];
                ulonglong2 hb = hBp[kql];
                ulonglong2 wz = wzp[(size_t)kql * JB];
                ulonglong2 wr2 = wrp[(size_t)kql * JB];
                ulonglong2 wn2 = wnp[(size_t)kql * JB];
                ffma2(azA, ha.x, wz.x);  ffma2(azA, ha.y, wz.y);
                ffma2(azB, hb.x, wz.x);  ffma2(azB, hb.y, wz.y);
                ffma2(arA, ha.x, wr2.x); ffma2(arA, ha.y, wr2.y);
                ffma2(arB, hb.x, wr2.x); ffma2(arB, hb.y, wr2.y);
                ffma2(anA, ha.x, wn2.x); ffma2(anA, ha.y, wn2.y);
                ffma2(anB, hb.x, wn2.x); ffma2(anB, hb.y, wn2.y);
            }
        }

        float hzA = pairsum(azA), hzB = pairsum(azB);
        float hrA = pairsum(arA), hrB = pairsum(arB);
        float hnA = pairsum(anA), hnB = pairsum(anB);

        {
            float z = 1.0f / (1.0f + __expf(-(xzA + hzA + bz)));
            float r = 1.0f / (1.0f + __expf(-(xrA + hrA + br)));
            float n = tanhf(xnA + r * (hnA + bn));
            __stcg(&h_out[(size_t)rowA * HH + jcol], (1.0f - z) * n + z * hpA);
        }
        {
            float z = 1.0f / (1.0f + __expf(-(xzB + hzB + bz)));
            float r = 1.0f / (1.0f + __expf(-(xrB + hrB + br)));
            float n = tanhf(xnB + r * (hnB + bn));
            __stcg(&h_out[(size_t)rowB * HH + jcol], (1.0f - z) * n + z * hpB);
        }

        if (t != TT - 1) grid_barrier();
    }
}

// ---------------------------------------------------------------------------
extern "C" void kernel_launch(void* const* d_in, const int* in_sizes, int n_in,
                              void* d_out, int out_size) {
    const float* x    = (const float*)d_in[0];
    const float* W_zx = (const float*)d_in[1];
    const float* W_zh = (const float*)d_in[2];
    const float* W_rx = (const float*)d_in[3];
    const float* W_rh = (const float*)d_in[4];
    const float* W_nx = (const float*)d_in[5];
    const float* W_nh = (const float*)d_in[6];
    const float* b_zx = (const float*)d_in[7];
    const float* b_zh = (const float*)d_in[8];
    const float* b_rx = (const float*)d_in[9];
    const float* b_rh = (const float*)d_in[10];
    const float* b_nx = (const float*)d_in[11];
    const float* b_nh = (const float*)d_in[12];
    float* out = (float*)d_out;

    cudaFuncSetAttribute(gru_scan_kernel,
                         cudaFuncAttributeMaxDynamicSharedMemorySize, SMEM_BYTES);

    xproj_kernel<<<dim3((BB * TT) / 128, HH / 128, 3), 256>>>(
        x, W_zx, W_rx, W_nx, b_zx, b_rx, b_nx);

    gru_scan_kernel<<<NCTA, 256, SMEM_BYTES>>>(
        out, W_zh, W_rh, W_nh, b_zh, b_rh, b_nh);
}